// round 3
// baseline (speedup 1.0000x reference)
#include <cuda_runtime.h>

// UnPatcher: 2-level inverse Haar DWT, fully fused.
// in : [8, 256, 96, 96]  f32   (channels = 16 out-ch x 4 (level2 m) x 4 (level1 n))
// out: [8, 16, 384, 384] f32
//
// out[b,c, 4i + 2*p1 + p, 4j + 2*q1 + q] =
//   sum_{m,n} in[b, c + 16m + 64n, i, j] * (-1)^{(m&1)p + (m>>1)q + (n&1)p1 + (n>>1)q1}
// (gain of each rescaled Haar level is exactly 1, so all coefficients are +/-1)

#define BATCH  8
#define CO     16
#define HI     96
#define WI     96
#define CHS    (CO * HI * WI)          // element stride between the 16 channel groups
#define TOTAL  (BATCH * CO * HI * WI)  // one thread per input spatial site = 1179648

__global__ void __launch_bounds__(256)
unpatcher_fused_kernel(const float* __restrict__ in, float* __restrict__ out)
{
    int t = blockIdx.x * 256 + threadIdx.x;
    if (t >= TOTAL) return;

    int j   = t % WI;
    int tmp = t / WI;
    int i   = tmp % HI;
    int bc  = tmp / HI;        // b*16 + c
    int b   = bc >> 4;
    int c   = bc & 15;

    // 16 coalesced loads: v[4n + m] = in[b, c + 16m + 64n, i, j]
    // channel offset 16m + 64n = 16*(m + 4n)  ->  element offset (m+4n)*CHS
    const float* __restrict__ base =
        in + (((size_t)(b * 256 + c)) * HI + i) * WI + j;

    float v[16];
#pragma unroll
    for (int k = 0; k < 16; k++)
        v[k] = __ldg(base + (size_t)k * CHS);

    // Stage 1: height transform (bits p = m&1 sign, p1 = n&1 sign)
    // For each width-coefficient combo wi = 2*nw + mw, produce 4 rows r = 2*p1 + p.
    float h[4][4];
#pragma unroll
    for (int nw = 0; nw < 2; nw++) {
#pragma unroll
        for (int mw = 0; mw < 2; mw++) {
            float c00 = v[8 * nw + 2 * mw + 0];  // nh=0, mh=0
            float c01 = v[8 * nw + 2 * mw + 1];  // nh=0, mh=1
            float c10 = v[8 * nw + 2 * mw + 4];  // nh=1, mh=0
            float c11 = v[8 * nw + 2 * mw + 5];  // nh=1, mh=1
            float u0 = c00 + c01, u1 = c00 - c01;    // over p  (level-2 height bit)
            float w0 = c10 + c11, w1 = c10 - c11;
            int wi_ = 2 * nw + mw;
            h[wi_][0] = u0 + w0;   // r=0: p=0,p1=0
            h[wi_][1] = u1 + w1;   // r=1: p=1,p1=0
            h[wi_][2] = u0 - w0;   // r=2: p=0,p1=1
            h[wi_][3] = u1 - w1;   // r=3: p=1,p1=1
        }
    }

    // Stage 2: width transform + vectorized float4 stores (one per patch row).
    // Output patch row r lives at out[bc, 4i + r, 4j .. 4j+3].
    float4* orow = (float4*)(out + ((size_t)bc * (4 * HI) + 4 * i) * (4 * WI)) + j;
    const int orow_stride = WI;  // one output row = 4*WI floats = WI float4s

#pragma unroll
    for (int r = 0; r < 4; r++) {
        float d00 = h[0][r];  // nw=0, mw=0
        float d01 = h[1][r];  // nw=0, mw=1
        float d10 = h[2][r];  // nw=1, mw=0
        float d11 = h[3][r];  // nw=1, mw=1
        float a0 = d00 + d01, a1 = d00 - d01;   // over q  (level-2 width bit)
        float b0 = d10 + d11, b1 = d10 - d11;
        float4 o;
        o.x = a0 + b0;   // s=0: q=0,q1=0
        o.y = a1 + b1;   // s=1: q=1,q1=0
        o.z = a0 - b0;   // s=2: q=0,q1=1
        o.w = a1 - b1;   // s=3: q=1,q1=1
        orow[r * orow_stride] = o;
    }
}

extern "C" void kernel_launch(void* const* d_in, const int* in_sizes, int n_in,
                              void* d_out, int out_size)
{
    const float* x = (const float*)d_in[0];
    float* y       = (float*)d_out;
    (void)in_sizes; (void)n_in; (void)out_size;

    int blocks = (TOTAL + 255) / 256;   // 4608 blocks of 256 threads
    unpatcher_fused_kernel<<<blocks, 256>>>(x, y);
}